// round 16
// baseline (speedup 1.0000x reference)
#include <cuda_runtime.h>

#define NUSERS 100000
#define NITEMS 100000
#define NN     200000
#define EMB    64
#define NB     3
#define NE     2000000
#define BATCH  4096
#define REG_W  0.0001f

#define NN3    (NB * NN)          // 600000
#define CAP    64                 // padded CSR capacity per node

// ---------------- scratch (static device globals) ----------------------------
__device__ float g_t0[(size_t)NN * EMB];
__device__ float g_t1[(size_t)NN * EMB];
__device__ float g_p0[(size_t)NN * EMB];                  // premult ping
__device__ float g_p1[(size_t)NN * EMB];                  // premult pong
__device__ int   g_cur[NN3];                              // cursor == degree
__device__ __align__(16) int g_slot[(size_t)NN3 * CAP];   // padded edge lists

// ---------------- zero cursors + loss ------------------------------------------
__global__ void k_zero(float* __restrict__ loss) {
    int i = blockIdx.x * blockDim.x + threadIdx.x;
    if (i == 0) *loss = 0.f;
    if (i < NN3) g_cur[i] = 0;
}

// ---------------- fused degree+bucket: blockIdx.y = behavior -------------------
__global__ void k_build(const int* __restrict__ edges) {
    int bi = blockIdx.y;
    const int* row = edges + ((size_t)bi * 2 + 0) * NE;
    const int* col = edges + ((size_t)bi * 2 + 1) * NE;
    int* cur  = g_cur  + bi * NN;
    int* slot = g_slot + (size_t)bi * NN * CAP;
    int i = blockIdx.x * blockDim.x + threadIdx.x;
    if (i < NE / 4) {
        int4 r = reinterpret_cast<const int4*>(row)[i];
        int4 c = reinterpret_cast<const int4*>(col)[i];
        int p;
        p = atomicAdd(&cur[c.x], 1); if (p < CAP) slot[(size_t)c.x * CAP + p] = r.x;
        p = atomicAdd(&cur[c.y], 1); if (p < CAP) slot[(size_t)c.y * CAP + p] = r.y;
        p = atomicAdd(&cur[c.z], 1); if (p < CAP) slot[(size_t)c.z * CAP + p] = r.z;
        p = atomicAdd(&cur[c.w], 1); if (p < CAP) slot[(size_t)c.w * CAP + p] = r.w;
    }
}

// ---------------- init: t0 = concat; p0 = t0 * dinv0 ---------------------------
__global__ void k_init(const float* __restrict__ ue, const float* __restrict__ ie) {
    int g = blockIdx.x * blockDim.x + threadIdx.x;   // NN*EMB/2 threads
    int i = g * 2;
    float2 v;
    if (i < NUSERS * EMB) v = *reinterpret_cast<const float2*>(&ue[i]);
    else                  v = *reinterpret_cast<const float2*>(&ie[i - NUSERS * EMB]);
    *reinterpret_cast<float2*>(&g_t0[i]) = v;
    int deg = g_cur[i >> 6];                          // behavior 0
    float d = (deg > 0) ? rsqrtf((float)deg) : 0.f;
    *reinterpret_cast<float2*>(&g_p0[i]) = make_float2(v.x * d, v.y * d);
}

// ---------------- fused: gather(8 nodes/warp) + shuffle matvec + norm ----------
// Phase A: gather 8 nodes' premultiplied sums; s stays in registers
//          (lane l holds components 2l, 2l+1 of each node's s).
// Phase B: matvec with W read twice per k (amortized 8x) and s broadcast
//          via register shuffles (zero smem traffic for s).
__global__ void __launch_bounds__(256)
k_gather(const float* __restrict__ tA, float* __restrict__ tB,
         const float* __restrict__ tpA, float* __restrict__ tpB,
         const float* __restrict__ W, const float* __restrict__ bias,
         const int* __restrict__ cur_b, const int* __restrict__ cur_nx,
         const int* __restrict__ slot_b) {
    __shared__ float Wt[64 * 65];     // Wt[j][k] = W[k][j]
    __shared__ float bsh[64];
    int t = threadIdx.x;
    for (int i = t; i < 4096; i += 256) {
        int k = i >> 6, j = i & 63;
        Wt[j * 65 + k] = W[i];
    }
    if (t < 64) bsh[t] = bias[t];
    __syncthreads();

    int w = t >> 5, l = t & 31;
    const float2* tp2 = reinterpret_cast<const float2*>(tpA);

    // NN % 64 == 0; each warp takes 8 consecutive nodes per sweep
    for (int node0 = (blockIdx.x * 8 + w) * 8; node0 < NN; node0 += gridDim.x * 64) {
        // ---- Phase A: gather 8 nodes; s components 2l,2l+1 stay in regs ----
        float sx[8], sy[8];
        #pragma unroll
        for (int n = 0; n < 8; n++) {
            int node = node0 + n;
            int deg = __ldg(&cur_b[node]);
            int nd = (deg < CAP) ? deg : CAP;
            const int4* s4 = reinterpret_cast<const int4*>(slot_b + (size_t)node * CAP);
            float ax0 = 0.f, ay0 = 0.f, ax1 = 0.f, ay1 = 0.f;
            int full4 = nd >> 2;
            for (int q = 0; q < full4; q++) {
                int4 r = __ldg(&s4[q]);
                float2 v0 = __ldg(&tp2[(size_t)r.x * 32 + l]);
                float2 v1 = __ldg(&tp2[(size_t)r.y * 32 + l]);
                float2 v2 = __ldg(&tp2[(size_t)r.z * 32 + l]);
                float2 v3 = __ldg(&tp2[(size_t)r.w * 32 + l]);
                ax0 += v0.x + v2.x;
                ay0 += v0.y + v2.y;
                ax1 += v1.x + v3.x;
                ay1 += v1.y + v3.y;
            }
            for (int j = full4 * 4; j < nd; j++) {
                int r = __ldg(&slot_b[(size_t)node * CAP + j]);
                float2 v = __ldg(&tp2[(size_t)r * 32 + l]);
                ax0 += v.x;
                ay0 += v.y;
            }
            float dn = (deg > 0) ? rsqrtf((float)deg) : 0.f;
            sx[n] = (ax0 + ax1) * dn;     // component 2l
            sy[n] = (ay0 + ay1) * dn;     // component 2l+1
        }

        // ---- Phase B: y[j] = sum_k s[k]*W[k][j] + b[j]; s via shuffles ----
        float y0[8], y1[8];
        float b0 = bsh[l], b1 = bsh[l + 32];
        #pragma unroll
        for (int n = 0; n < 8; n++) { y0[n] = b0; y1[n] = b1; }
        #pragma unroll 8
        for (int k = 0; k < 64; k++) {
            float w0 = Wt[l * 65 + k];          // W[k][l]
            float w1 = Wt[(l + 32) * 65 + k];   // W[k][l+32]
            int src = k >> 1;
            #pragma unroll
            for (int n = 0; n < 8; n++) {
                float sk = __shfl_sync(0xffffffffu, (k & 1) ? sy[n] : sx[n], src);
                y0[n] += sk * w0;
                y1[n] += sk * w1;
            }
        }

        // ---- norm + residual + pong premult, per node ----
        #pragma unroll
        for (int n = 0; n < 8; n++) {
            int node = node0 + n;
            float ss = y0[n] * y0[n] + y1[n] * y1[n];
            for (int o = 16; o; o >>= 1) ss += __shfl_xor_sync(0xffffffffu, ss, o);
            float inv = 1.f / fmaxf(sqrtf(ss), 1e-12f);
            size_t base = (size_t)node * 64;
            float z0 = tA[base + l]      + y0[n] * inv;
            float z1 = tA[base + l + 32] + y1[n] * inv;
            tB[base + l]      = z0;
            tB[base + l + 32] = z1;
            int degn = __ldg(&cur_nx[node]);
            float dnx = (degn > 0) ? rsqrtf((float)degn) : 0.f;
            tpB[base + l]      = z0 * dnx;
            tpB[base + l + 32] = z1 * dnx;
        }
    }
}

// ---------------- BPR loss ------------------------------------------------------
__global__ void k_bpr(const float* __restrict__ tot, const int* __restrict__ bd,
                      float* __restrict__ loss, int bi) {
    int b = blockIdx.x * 8 + (threadIdx.x >> 5);
    int l = threadIdx.x & 31;
    if (b >= BATCH) return;
    const int* q = bd + ((size_t)b * NB + bi) * 3;
    int u = q[0], ip = q[1], in_ = q[2];
    const float2 uu = *reinterpret_cast<const float2*>(&tot[(size_t)u * 64 + l * 2]);
    const float2 pp = *reinterpret_cast<const float2*>(&tot[((size_t)NUSERS + ip) * 64 + l * 2]);
    const float2 nn = *reinterpret_cast<const float2*>(&tot[((size_t)NUSERS + in_) * 64 + l * 2]);
    float s0 = uu.x * pp.x + uu.y * pp.y;
    float s1 = uu.x * nn.x + uu.y * nn.y;
    for (int o = 16; o; o >>= 1) {
        s0 += __shfl_xor_sync(0xffffffffu, s0, o);
        s1 += __shfl_xor_sync(0xffffffffu, s1, o);
    }
    if (l == 0) {
        float d = s0 - s1;
        float ls = fminf(d, 0.f) - log1pf(expf(-fabsf(d)));
        atomicAdd(loss, -ls / (float)BATCH);
    }
}

// ---------------- reg term (loss zeroed by k_zero) ------------------------------
__global__ void k_reg(const float* __restrict__ ue, const float* __restrict__ ie,
                      float* __restrict__ loss) {
    int gid = blockIdx.x * blockDim.x + threadIdx.x;
    int stride = gridDim.x * blockDim.x;
    float s = 0.f;
    for (int i = gid; i < NN * EMB; i += stride) {
        float v = (i < NUSERS * EMB) ? ue[i] : ie[i - NUSERS * EMB];
        s += v * v;
    }
    for (int o = 16; o; o >>= 1) s += __shfl_xor_sync(0xffffffffu, s, o);
    __shared__ float sm[8];
    int w = threadIdx.x >> 5, l = threadIdx.x & 31;
    if (l == 0) sm[w] = s;
    __syncthreads();
    if (threadIdx.x == 0) {
        float t = 0.f;
        #pragma unroll
        for (int k = 0; k < 8; k++) t += sm[k];
        atomicAdd(loss, t * (REG_W * 0.5f / (float)BATCH));
    }
}

// ---------------- launcher ------------------------------------------------------
extern "C" void kernel_launch(void* const* d_in, const int* in_sizes, int n_in,
                              void* d_out, int out_size) {
    const float* ue    = (const float*)d_in[0];
    const float* ie    = (const float*)d_in[1];
    const float* gw    = (const float*)d_in[2];   // [3,64,64]
    const float* gb    = (const float*)d_in[3];   // [3,64]
    const int*   edges = (const int*)d_in[4];     // [3,2,NE] int32
    const int*   bd    = (const int*)d_in[5];     // [BATCH,3,3] int32
    float* loss = (float*)d_out;

    float* tb[2] = { (float*)0, (float*)0 };
    float* pb[2] = { (float*)0, (float*)0 };
    cudaGetSymbolAddress((void**)&tb[0], g_t0);
    cudaGetSymbolAddress((void**)&tb[1], g_t1);
    cudaGetSymbolAddress((void**)&pb[0], g_p0);
    cudaGetSymbolAddress((void**)&pb[1], g_p1);
    int* cur_base = (int*)0;
    cudaGetSymbolAddress((void**)&cur_base, g_cur);
    int* slot_base = (int*)0;
    cudaGetSymbolAddress((void**)&slot_base, g_slot);

    // 1: zero cursors + loss
    k_zero<<<(NN3 + 255) / 256, 256>>>(loss);
    // 2: fused degree+bucket for all behaviors
    {
        dim3 g((NE / 4 + 255) / 256, NB);
        k_build<<<g, 256>>>(edges);
    }
    // 3: init embeddings + premultiplied copy (behavior 0)
    k_init<<<NN * EMB / 2 / 256, 256>>>(ue, ie);

    // 4..9: gather/bpr chain (gather0 is launch #4 -> profiled)
    for (int bi = 0; bi < NB; bi++) {
        const float* tA  = tb[bi & 1];
        float*       tB  = tb[(bi + 1) & 1];
        const float* tpA = pb[bi & 1];
        float*       tpB = pb[(bi + 1) & 1];
        int bn = (bi + 1 < NB) ? bi + 1 : 0;
        k_gather<<<1184, 256>>>(tA, tB, tpA, tpB,
                                gw + (size_t)bi * EMB * EMB, gb + bi * EMB,
                                cur_base + (size_t)bi * NN, cur_base + (size_t)bn * NN,
                                slot_base + (size_t)bi * NN * CAP);
        k_bpr<<<(BATCH + 7) / 8, 256>>>(tB, bd, loss, bi);
    }
    // 10: reg term
    k_reg<<<1024, 256>>>(ue, ie, loss);
}

// round 17
// speedup vs baseline: 1.1065x; 1.1065x over previous
#include <cuda_runtime.h>

#define NUSERS 100000
#define NITEMS 100000
#define NN     200000
#define EMB    64
#define NB     3
#define NE     2000000
#define BATCH  4096
#define REG_W  0.0001f

#define NN3    (NB * NN)          // 600000
#define CAP    64                 // padded CSR capacity per node

// ---------------- scratch (static device globals) ----------------------------
__device__ float g_t0[(size_t)NN * EMB];
__device__ float g_t1[(size_t)NN * EMB];
__device__ float g_p0[(size_t)NN * EMB];                  // premult ping
__device__ float g_p1[(size_t)NN * EMB];                  // premult pong
__device__ int   g_cur[NN3];                              // cursor == degree
__device__ __align__(16) int g_slot[(size_t)NN3 * CAP];   // padded edge lists

// ---------------- zero cursors + loss ------------------------------------------
__global__ void k_zero(float* __restrict__ loss) {
    int i = blockIdx.x * blockDim.x + threadIdx.x;
    if (i == 0) *loss = 0.f;
    if (i < NN3) g_cur[i] = 0;
}

// ---------------- fused degree+bucket: blockIdx.y = behavior -------------------
__global__ void k_build(const int* __restrict__ edges) {
    int bi = blockIdx.y;
    const int* row = edges + ((size_t)bi * 2 + 0) * NE;
    const int* col = edges + ((size_t)bi * 2 + 1) * NE;
    int* cur  = g_cur  + bi * NN;
    int* slot = g_slot + (size_t)bi * NN * CAP;
    int i = blockIdx.x * blockDim.x + threadIdx.x;
    if (i < NE / 4) {
        int4 r = reinterpret_cast<const int4*>(row)[i];
        int4 c = reinterpret_cast<const int4*>(col)[i];
        int p;
        p = atomicAdd(&cur[c.x], 1); if (p < CAP) slot[(size_t)c.x * CAP + p] = r.x;
        p = atomicAdd(&cur[c.y], 1); if (p < CAP) slot[(size_t)c.y * CAP + p] = r.y;
        p = atomicAdd(&cur[c.z], 1); if (p < CAP) slot[(size_t)c.z * CAP + p] = r.z;
        p = atomicAdd(&cur[c.w], 1); if (p < CAP) slot[(size_t)c.w * CAP + p] = r.w;
    }
}

// ---------------- init: t0 = concat; p0 = t0 * dinv0 ---------------------------
__global__ void k_init(const float* __restrict__ ue, const float* __restrict__ ie) {
    int g = blockIdx.x * blockDim.x + threadIdx.x;   // NN*EMB/2 threads
    int i = g * 2;
    float2 v;
    if (i < NUSERS * EMB) v = *reinterpret_cast<const float2*>(&ue[i]);
    else                  v = *reinterpret_cast<const float2*>(&ie[i - NUSERS * EMB]);
    *reinterpret_cast<float2*>(&g_t0[i]) = v;
    int deg = g_cur[i >> 6];                          // behavior 0
    float d = (deg > 0) ? rsqrtf((float)deg) : 0.f;
    *reinterpret_cast<float2*>(&g_p0[i]) = make_float2(v.x * d, v.y * d);
}

// ---------------- fused: gather(4 nodes/warp) + float4 matvec + norm -----------
// Phase A: gather 4 nodes' premultiplied sums into smem.
// Phase B: float4 LDS for both W (stride 68, conflict-free) and s broadcasts.
__global__ void __launch_bounds__(256)
k_gather(const float* __restrict__ tA, float* __restrict__ tB,
         const float* __restrict__ tpA, float* __restrict__ tpB,
         const float* __restrict__ W, const float* __restrict__ bias,
         const int* __restrict__ cur_b, const int* __restrict__ cur_nx,
         const int* __restrict__ slot_b) {
    __shared__ __align__(16) float Wt[64 * 68];   // Wt[j][k] = W[k][j], stride 68
    __shared__ __align__(16) float sbuf[8][4 * 64];
    __shared__ float bsh[64];
    int t = threadIdx.x;
    for (int i = t; i < 4096; i += 256) {
        int k = i >> 6, j = i & 63;
        Wt[j * 68 + k] = W[i];
    }
    if (t < 64) bsh[t] = bias[t];
    __syncthreads();

    int w = t >> 5, l = t & 31;
    const float2* tp2 = reinterpret_cast<const float2*>(tpA);
    float* sb = sbuf[w];
    const float4* w0p = reinterpret_cast<const float4*>(&Wt[l * 68]);
    const float4* w1p = reinterpret_cast<const float4*>(&Wt[(l + 32) * 68]);

    // NN % 32 == 0, each warp takes 4 consecutive nodes
    for (int node0 = blockIdx.x * 32 + w * 4; node0 < NN; node0 += gridDim.x * 32) {
        // ---- Phase A: gather 4 nodes ----
        #pragma unroll
        for (int n = 0; n < 4; n++) {
            int node = node0 + n;
            int deg = __ldg(&cur_b[node]);
            int nd = (deg < CAP) ? deg : CAP;
            const int4* s4 = reinterpret_cast<const int4*>(slot_b + (size_t)node * CAP);
            float ax0 = 0.f, ay0 = 0.f, ax1 = 0.f, ay1 = 0.f;
            int full4 = nd >> 2;
            for (int q = 0; q < full4; q++) {
                int4 r = __ldg(&s4[q]);
                float2 v0 = __ldg(&tp2[(size_t)r.x * 32 + l]);
                float2 v1 = __ldg(&tp2[(size_t)r.y * 32 + l]);
                float2 v2 = __ldg(&tp2[(size_t)r.z * 32 + l]);
                float2 v3 = __ldg(&tp2[(size_t)r.w * 32 + l]);
                ax0 += v0.x + v2.x;
                ay0 += v0.y + v2.y;
                ax1 += v1.x + v3.x;
                ay1 += v1.y + v3.y;
            }
            for (int j = full4 * 4; j < nd; j++) {
                int r = __ldg(&slot_b[(size_t)node * CAP + j]);
                float2 v = __ldg(&tp2[(size_t)r * 32 + l]);
                ax0 += v.x;
                ay0 += v.y;
            }
            float dn = (deg > 0) ? rsqrtf((float)deg) : 0.f;
            sb[n * 64 + 2 * l]     = (ax0 + ax1) * dn;
            sb[n * 64 + 2 * l + 1] = (ay0 + ay1) * dn;
        }
        __syncwarp();

        // ---- Phase B: float4 matvec (W amortized 4x, 16B broadcasts) ----
        float y0[4], y1[4];
        float b0 = bsh[l], b1 = bsh[l + 32];
        #pragma unroll
        for (int n = 0; n < 4; n++) { y0[n] = b0; y1[n] = b1; }
        #pragma unroll 4
        for (int qq = 0; qq < 16; qq++) {
            float4 w0 = w0p[qq];
            float4 w1 = w1p[qq];
            #pragma unroll
            for (int n = 0; n < 4; n++) {
                float4 s4 = *reinterpret_cast<const float4*>(&sb[n * 64 + 4 * qq]);
                y0[n] += s4.x * w0.x + s4.y * w0.y + s4.z * w0.z + s4.w * w0.w;
                y1[n] += s4.x * w1.x + s4.y * w1.y + s4.z * w1.z + s4.w * w1.w;
            }
        }
        __syncwarp();

        // ---- norm + residual + pong premult, per node ----
        #pragma unroll
        for (int n = 0; n < 4; n++) {
            int node = node0 + n;
            float ss = y0[n] * y0[n] + y1[n] * y1[n];
            for (int o = 16; o; o >>= 1) ss += __shfl_xor_sync(0xffffffffu, ss, o);
            float inv = 1.f / fmaxf(sqrtf(ss), 1e-12f);
            size_t base = (size_t)node * 64;
            float z0 = tA[base + l]      + y0[n] * inv;
            float z1 = tA[base + l + 32] + y1[n] * inv;
            tB[base + l]      = z0;
            tB[base + l + 32] = z1;
            int degn = __ldg(&cur_nx[node]);
            float dnx = (degn > 0) ? rsqrtf((float)degn) : 0.f;
            tpB[base + l]      = z0 * dnx;
            tpB[base + l + 32] = z1 * dnx;
        }
        __syncwarp();
    }
}

// ---------------- BPR loss ------------------------------------------------------
__global__ void k_bpr(const float* __restrict__ tot, const int* __restrict__ bd,
                      float* __restrict__ loss, int bi) {
    int b = blockIdx.x * 8 + (threadIdx.x >> 5);
    int l = threadIdx.x & 31;
    if (b >= BATCH) return;
    const int* q = bd + ((size_t)b * NB + bi) * 3;
    int u = q[0], ip = q[1], in_ = q[2];
    const float2 uu = *reinterpret_cast<const float2*>(&tot[(size_t)u * 64 + l * 2]);
    const float2 pp = *reinterpret_cast<const float2*>(&tot[((size_t)NUSERS + ip) * 64 + l * 2]);
    const float2 nn = *reinterpret_cast<const float2*>(&tot[((size_t)NUSERS + in_) * 64 + l * 2]);
    float s0 = uu.x * pp.x + uu.y * pp.y;
    float s1 = uu.x * nn.x + uu.y * nn.y;
    for (int o = 16; o; o >>= 1) {
        s0 += __shfl_xor_sync(0xffffffffu, s0, o);
        s1 += __shfl_xor_sync(0xffffffffu, s1, o);
    }
    if (l == 0) {
        float d = s0 - s1;
        float ls = fminf(d, 0.f) - log1pf(expf(-fabsf(d)));
        atomicAdd(loss, -ls / (float)BATCH);
    }
}

// ---------------- reg term (loss zeroed by k_zero) ------------------------------
__global__ void k_reg(const float* __restrict__ ue, const float* __restrict__ ie,
                      float* __restrict__ loss) {
    int gid = blockIdx.x * blockDim.x + threadIdx.x;
    int stride = gridDim.x * blockDim.x;
    float s = 0.f;
    for (int i = gid; i < NN * EMB; i += stride) {
        float v = (i < NUSERS * EMB) ? ue[i] : ie[i - NUSERS * EMB];
        s += v * v;
    }
    for (int o = 16; o; o >>= 1) s += __shfl_xor_sync(0xffffffffu, s, o);
    __shared__ float sm[8];
    int w = threadIdx.x >> 5, l = threadIdx.x & 31;
    if (l == 0) sm[w] = s;
    __syncthreads();
    if (threadIdx.x == 0) {
        float t = 0.f;
        #pragma unroll
        for (int k = 0; k < 8; k++) t += sm[k];
        atomicAdd(loss, t * (REG_W * 0.5f / (float)BATCH));
    }
}

// ---------------- launcher ------------------------------------------------------
extern "C" void kernel_launch(void* const* d_in, const int* in_sizes, int n_in,
                              void* d_out, int out_size) {
    const float* ue    = (const float*)d_in[0];
    const float* ie    = (const float*)d_in[1];
    const float* gw    = (const float*)d_in[2];   // [3,64,64]
    const float* gb    = (const float*)d_in[3];   // [3,64]
    const int*   edges = (const int*)d_in[4];     // [3,2,NE] int32
    const int*   bd    = (const int*)d_in[5];     // [BATCH,3,3] int32
    float* loss = (float*)d_out;

    float* tb[2] = { (float*)0, (float*)0 };
    float* pb[2] = { (float*)0, (float*)0 };
    cudaGetSymbolAddress((void**)&tb[0], g_t0);
    cudaGetSymbolAddress((void**)&tb[1], g_t1);
    cudaGetSymbolAddress((void**)&pb[0], g_p0);
    cudaGetSymbolAddress((void**)&pb[1], g_p1);
    int* cur_base = (int*)0;
    cudaGetSymbolAddress((void**)&cur_base, g_cur);
    int* slot_base = (int*)0;
    cudaGetSymbolAddress((void**)&slot_base, g_slot);

    // 1: zero cursors + loss
    k_zero<<<(NN3 + 255) / 256, 256>>>(loss);
    // 2: fused degree+bucket for all behaviors
    {
        dim3 g((NE / 4 + 255) / 256, NB);
        k_build<<<g, 256>>>(edges);
    }
    // 3: init embeddings + premultiplied copy (behavior 0)
    k_init<<<NN * EMB / 2 / 256, 256>>>(ue, ie);

    // 4..9: gather/bpr chain (gather0 is launch #4 -> profiled)
    for (int bi = 0; bi < NB; bi++) {
        const float* tA  = tb[bi & 1];
        float*       tB  = tb[(bi + 1) & 1];
        const float* tpA = pb[bi & 1];
        float*       tpB = pb[(bi + 1) & 1];
        int bn = (bi + 1 < NB) ? bi + 1 : 0;
        k_gather<<<1184, 256>>>(tA, tB, tpA, tpB,
                                gw + (size_t)bi * EMB * EMB, gb + bi * EMB,
                                cur_base + (size_t)bi * NN, cur_base + (size_t)bn * NN,
                                slot_base + (size_t)bi * NN * CAP);
        k_bpr<<<(BATCH + 7) / 8, 256>>>(tB, bd, loss, bi);
    }
    // 10: reg term
    k_reg<<<1024, 256>>>(ue, ie, loss);
}